// round 3
// baseline (speedup 1.0000x reference)
#include <cuda_runtime.h>
#include <cstdint>

// Problem constants
#define BB 2
#define HH 256
#define WW 256
#define CC 256
#define WS 8
#define SHIFT 4
#define NH 8
#define HD 32
#define OUTC 256
#define NWIN 1024      // (H/WS)*(W/WS)
#define PP 64          // WS*WS
#define MROWS 131072   // B*NWIN*PP per stream

// Scratch (device globals; no runtime allocation allowed)
// qkv layout: [stream][qkv][b][win][head][p][d]
__device__ float g_qkv[2u*3u*BB*NWIN*NH*PP*HD];        // 201,326,592 floats
// attn out layout: [stream][b][win][p][C]  (C = head*32+d)
__device__ float g_attn[2u*BB*NWIN*PP*CC];             // 67,108,864 floats
// bias table: [stream][head][p][q]
__device__ float g_bias[2*NH*PP*PP];                   // 65,536 floats

// ---------------------------------------------------------------------------
// Kernel 0: bias table from rel (NH,15,15)
// ---------------------------------------------------------------------------
__global__ void bias_kernel(const float* __restrict__ rel1,
                            const float* __restrict__ rel2)
{
    int idx = blockIdx.x * blockDim.x + threadIdx.x;   // 0 .. 65535
    int s    = idx >> 15;
    int head = (idx >> 12) & 7;
    int p    = (idx >> 6) & 63;
    int q    = idx & 63;
    const float* rel = s ? rel2 : rel1;
    int a = (p >> 3) - (q >> 3) + 7;
    int b = (p & 7) - (q & 7) + 7;
    g_bias[idx] = rel[head * 225 + a * 15 + b];
}

// ---------------------------------------------------------------------------
// Kernel 1: QKV GEMM with fused roll + window gather.
// A: gathered emb rows (M=131072, K=256)   B: Wqkv (256 x 768)
// 128x128x8 tiling, 256 threads, 8x8 register tiles.
// ---------------------------------------------------------------------------
__global__ __launch_bounds__(256)
void qkv_gemm(const float* __restrict__ emb1, const float* __restrict__ emb2,
              const float* __restrict__ Wqkv1, const float* __restrict__ bqkv1,
              const float* __restrict__ Wqkv2, const float* __restrict__ bqkv2)
{
    const int s = blockIdx.z;
    const float* __restrict__ emb = s ? emb2 : emb1;
    const float* __restrict__ Wq  = s ? Wqkv2 : Wqkv1;
    const float* __restrict__ bq  = s ? bqkv2 : bqkv1;

    __shared__ float As[8][128];   // transposed A tile
    __shared__ float Bs[8][128];

    const int tid      = threadIdx.x;
    const int rowBlock = blockIdx.y;   // 0..1023
    const int colBlock = blockIdx.x;   // 0..5

    // A-tile loader mapping: one float4 per thread per k-iter
    const int arow  = tid >> 1;          // 0..127
    const int apart = (tid & 1) * 4;     // 0 or 4
    const int R     = rowBlock * 128 + arow;
    {
        // decode token -> rolled source pixel
    }
    const int p_   = R & 63;
    const int win_ = (R >> 6) & 1023;
    const int b_   = R >> 16;
    const int hsrc = (((win_ >> 5) << 3) + (p_ >> 3) + SHIFT) & 255;
    const int wsrc = ((win_ & 31) << 3) + (p_ & 7);
    const float* aBase = emb + ((((size_t)b_ * HH + hsrc) * WW + wsrc) * CC);

    // B-tile loader mapping
    const int brow = tid >> 5;          // 0..7
    const int bcol = (tid & 31) * 4;    // 0..124

    float acc[8][8];
#pragma unroll
    for (int i = 0; i < 8; i++)
#pragma unroll
        for (int j = 0; j < 8; j++) acc[i][j] = 0.f;

    const int ty = tid >> 4, tx = tid & 15;

    for (int k0 = 0; k0 < CC; k0 += 8) {
        float4 av = *reinterpret_cast<const float4*>(aBase + k0 + apart);
        float4 bv = *reinterpret_cast<const float4*>(
            Wq + (size_t)(k0 + brow) * 768 + colBlock * 128 + bcol);
        As[apart + 0][arow] = av.x;
        As[apart + 1][arow] = av.y;
        As[apart + 2][arow] = av.z;
        As[apart + 3][arow] = av.w;
        *reinterpret_cast<float4*>(&Bs[brow][bcol]) = bv;
        __syncthreads();
#pragma unroll
        for (int k = 0; k < 8; ++k) {
            float af[8], bf[8];
            *reinterpret_cast<float4*>(&af[0]) = *reinterpret_cast<const float4*>(&As[k][ty * 4]);
            *reinterpret_cast<float4*>(&af[4]) = *reinterpret_cast<const float4*>(&As[k][64 + ty * 4]);
            *reinterpret_cast<float4*>(&bf[0]) = *reinterpret_cast<const float4*>(&Bs[k][tx * 4]);
            *reinterpret_cast<float4*>(&bf[4]) = *reinterpret_cast<const float4*>(&Bs[k][64 + tx * 4]);
#pragma unroll
            for (int i = 0; i < 8; i++)
#pragma unroll
                for (int j = 0; j < 8; j++)
                    acc[i][j] += af[i] * bf[j];
        }
        __syncthreads();
    }

    // epilogue: add bias, scatter to q/k/v layout
#pragma unroll
    for (int ih = 0; ih < 2; ih++) {
#pragma unroll
        for (int i = 0; i < 4; i++) {
            int r  = rowBlock * 128 + ih * 64 + ty * 4 + i;
            int pr = r & 63;
            int wr = (r >> 6) & 1023;
            int br = r >> 16;
#pragma unroll
            for (int jh = 0; jh < 2; jh++) {
#pragma unroll
                for (int j = 0; j < 4; j++) {
                    int n = colBlock * 128 + jh * 64 + tx * 4 + j;   // 0..767
                    float v = acc[ih * 4 + i][jh * 4 + j] + bq[n];
                    int qkv  = n >> 8;
                    int head = (n >> 5) & 7;
                    int d    = n & 31;
                    size_t idx = (((((size_t)s * 3 + qkv) * BB + br) * NWIN + wr) * NH + head)
                                     * ((size_t)PP * HD)
                                 + (size_t)pr * HD + d;
                    g_qkv[idx] = v;
                }
            }
        }
    }
}

// ---------------------------------------------------------------------------
// Kernel 2: windowed cross-attention.
// block = (b*win, head, stream). q from stream s, k/v from stream 1-s.
// ---------------------------------------------------------------------------
__global__ __launch_bounds__(128)
void attn_kernel()
{
    const int s    = blockIdx.z;
    const int head = blockIdx.y;
    const int bw   = blockIdx.x;           // 0..2047
    const int b    = bw >> 10;
    const int win  = bw & 1023;
    const int os   = 1 - s;

    __shared__ float qs[64][36];
    __shared__ float ks[64][36];
    __shared__ float vs[64][36];
    __shared__ float sim[64][65];

    const int tid = threadIdx.x;           // 128 threads

    const size_t tile = (size_t)PP * HD;   // 2048
    const size_t qbase = (((((size_t)s  * 3 + 0) * BB + b) * NWIN + win) * NH + head) * tile;
    const size_t kbase = (((((size_t)os * 3 + 1) * BB + b) * NWIN + win) * NH + head) * tile;
    const size_t vbase = (((((size_t)os * 3 + 2) * BB + b) * NWIN + win) * NH + head) * tile;

    // load q/k/v tiles (2048 floats each)
#pragma unroll
    for (int it = 0; it < 4; ++it) {
        int e = tid * 4 + it * 512;        // float offset, multiple of 4
        int p = e >> 5, d = e & 31;
        float4 vq = *reinterpret_cast<const float4*>(&g_qkv[qbase + e]);
        qs[p][d] = vq.x; qs[p][d+1] = vq.y; qs[p][d+2] = vq.z; qs[p][d+3] = vq.w;
        float4 vk = *reinterpret_cast<const float4*>(&g_qkv[kbase + e]);
        ks[p][d] = vk.x; ks[p][d+1] = vk.y; ks[p][d+2] = vk.z; ks[p][d+3] = vk.w;
        float4 vv = *reinterpret_cast<const float4*>(&g_qkv[vbase + e]);
        vs[p][d] = vv.x; vs[p][d+1] = vv.y; vs[p][d+2] = vv.z; vs[p][d+3] = vv.w;
    }
    // load bias into sim (coalesced)
    const size_t bb = ((size_t)s * NH + head) * 4096;
#pragma unroll
    for (int e = 0; e < 32; ++e) {
        int idx = tid + e * 128;
        sim[idx >> 6][idx & 63] = g_bias[bb + idx];
    }
    __syncthreads();

    // sim = q.k^T * scale + bias, masked
    const int p  = tid >> 1;
    const int qb = (tid & 1) * 32;
    float qreg[32];
#pragma unroll
    for (int d = 0; d < 32; d += 4) {
        float4 v = *reinterpret_cast<const float4*>(&qs[p][d]);
        qreg[d] = v.x; qreg[d+1] = v.y; qreg[d+2] = v.z; qreg[d+3] = v.w;
    }
    const int  ip = p >> 3, jp = p & 7;
    const bool mh = ((win >> 5) == 31);
    const bool mw = ((win & 31) == 31);
    const float scale = 0.17677669529663687f;   // 1/sqrt(32)

#pragma unroll 4
    for (int qi = 0; qi < 32; ++qi) {
        int qq = qb + qi;
        float acc = 0.f;
#pragma unroll
        for (int d = 0; d < 32; d += 4) {
            float4 kv = *reinterpret_cast<const float4*>(&ks[qq][d]);
            acc += qreg[d] * kv.x + qreg[d+1] * kv.y + qreg[d+2] * kv.z + qreg[d+3] * kv.w;
        }
        float bias = sim[p][qq];
        float val  = acc * scale + bias;
        int iq = qq >> 3, jq = qq & 7;
        bool masked = (mh && ((ip < 4) != (iq < 4))) || (mw && ((jp < 4) != (jq < 4)));
        sim[p][qq] = masked ? -1e30f : val;
    }
    __syncthreads();

    // softmax: one thread per row
    if (tid < 64) {
        float m = -1e30f;
#pragma unroll 8
        for (int q = 0; q < 64; ++q) m = fmaxf(m, sim[tid][q]);
        float sum = 0.f;
#pragma unroll 8
        for (int q = 0; q < 64; ++q) {
            float e = __expf(sim[tid][q] - m);
            sim[tid][q] = e;
            sum += e;
        }
        float inv = 1.f / sum;
#pragma unroll 8
        for (int q = 0; q < 64; ++q) sim[tid][q] *= inv;
    }
    __syncthreads();

    // o = pr @ v : thread handles (row p, 16 d-values)
    const int db = (tid & 1) * 16;
    float o[16];
#pragma unroll
    for (int j = 0; j < 16; j++) o[j] = 0.f;
#pragma unroll 4
    for (int qc = 0; qc < 64; ++qc) {
        float pr = sim[p][qc];
#pragma unroll
        for (int j = 0; j < 16; j += 4) {
            float4 vv = *reinterpret_cast<const float4*>(&vs[qc][db + j]);
            o[j]   += pr * vv.x;
            o[j+1] += pr * vv.y;
            o[j+2] += pr * vv.z;
            o[j+3] += pr * vv.w;
        }
    }
    size_t ob = (size_t)s * ((size_t)BB * NWIN * PP * CC)
              + ((((size_t)b * NWIN + win) * PP + p) * CC)
              + (size_t)head * HD + db;
#pragma unroll
    for (int j = 0; j < 16; j += 4) {
        float4 vv = make_float4(o[j], o[j+1], o[j+2], o[j+3]);
        *reinterpret_cast<float4*>(&g_attn[ob + j]) = vv;
    }
}

// ---------------------------------------------------------------------------
// Kernel 3: output projection GEMM + fused unwindow + roll scatter.
// A: g_attn (M=131072, K=256)  B: Wo (256 x 256)
// ---------------------------------------------------------------------------
__global__ __launch_bounds__(256)
void proj_gemm(const float* __restrict__ Wo1, const float* __restrict__ bo1,
               const float* __restrict__ Wo2, const float* __restrict__ bo2,
               float* __restrict__ out)
{
    const int s = blockIdx.z;
    const float* __restrict__ Wo = s ? Wo2 : Wo1;
    const float* __restrict__ bo = s ? bo2 : bo1;
    float* __restrict__ dst = out + (size_t)s * ((size_t)BB * HH * WW * OUTC);

    __shared__ float As[8][128];
    __shared__ float Bs[8][128];

    const int tid      = threadIdx.x;
    const int rowBlock = blockIdx.y;   // 0..1023
    const int colBlock = blockIdx.x;   // 0..1

    const int arow  = tid >> 1;
    const int apart = (tid & 1) * 4;
    const int R     = rowBlock * 128 + arow;
    const float* aBase = g_attn + (size_t)s * ((size_t)BB * NWIN * PP * CC) + (size_t)R * CC;

    const int brow = tid >> 5;
    const int bcol = (tid & 31) * 4;

    float acc[8][8];
#pragma unroll
    for (int i = 0; i < 8; i++)
#pragma unroll
        for (int j = 0; j < 8; j++) acc[i][j] = 0.f;

    const int ty = tid >> 4, tx = tid & 15;

    for (int k0 = 0; k0 < CC; k0 += 8) {
        float4 av = *reinterpret_cast<const float4*>(aBase + k0 + apart);
        float4 bv = *reinterpret_cast<const float4*>(
            Wo + (size_t)(k0 + brow) * OUTC + colBlock * 128 + bcol);
        As[apart + 0][arow] = av.x;
        As[apart + 1][arow] = av.y;
        As[apart + 2][arow] = av.z;
        As[apart + 3][arow] = av.w;
        *reinterpret_cast<float4*>(&Bs[brow][bcol]) = bv;
        __syncthreads();
#pragma unroll
        for (int k = 0; k < 8; ++k) {
            float af[8], bf[8];
            *reinterpret_cast<float4*>(&af[0]) = *reinterpret_cast<const float4*>(&As[k][ty * 4]);
            *reinterpret_cast<float4*>(&af[4]) = *reinterpret_cast<const float4*>(&As[k][64 + ty * 4]);
            *reinterpret_cast<float4*>(&bf[0]) = *reinterpret_cast<const float4*>(&Bs[k][tx * 4]);
            *reinterpret_cast<float4*>(&bf[4]) = *reinterpret_cast<const float4*>(&Bs[k][64 + tx * 4]);
#pragma unroll
            for (int i = 0; i < 8; i++)
#pragma unroll
                for (int j = 0; j < 8; j++)
                    acc[i][j] += af[i] * bf[j];
        }
        __syncthreads();
    }

    // epilogue: add bias, unwindow + roll scatter
#pragma unroll
    for (int ih = 0; ih < 2; ih++) {
#pragma unroll
        for (int i = 0; i < 4; i++) {
            int r  = rowBlock * 128 + ih * 64 + ty * 4 + i;
            int pr = r & 63;
            int wr = (r >> 6) & 1023;
            int br = r >> 16;
            int hout = (((wr >> 5) << 3) + (pr >> 3) + SHIFT) & 255;
            int wout = ((wr & 31) << 3) + (pr & 7);
            size_t rowbase = (((size_t)br * HH + hout) * WW + wout) * OUTC;
#pragma unroll
            for (int jh = 0; jh < 2; jh++) {
                int n0 = colBlock * 128 + jh * 64 + tx * 4;
                float4 vv;
                vv.x = acc[ih * 4 + i][jh * 4 + 0] + bo[n0 + 0];
                vv.y = acc[ih * 4 + i][jh * 4 + 1] + bo[n0 + 1];
                vv.z = acc[ih * 4 + i][jh * 4 + 2] + bo[n0 + 2];
                vv.w = acc[ih * 4 + i][jh * 4 + 3] + bo[n0 + 3];
                *reinterpret_cast<float4*>(&dst[rowbase + n0]) = vv;
            }
        }
    }
}

// ---------------------------------------------------------------------------
// Launch
// ---------------------------------------------------------------------------
extern "C" void kernel_launch(void* const* d_in, const int* in_sizes, int n_in,
                              void* d_out, int out_size)
{
    const float* emb1  = (const float*)d_in[0];
    const float* emb2  = (const float*)d_in[1];
    const float* Wqkv1 = (const float*)d_in[2];
    const float* bqkv1 = (const float*)d_in[3];
    const float* Wqkv2 = (const float*)d_in[4];
    const float* bqkv2 = (const float*)d_in[5];
    const float* rel1  = (const float*)d_in[6];
    const float* rel2  = (const float*)d_in[7];
    const float* Wo1   = (const float*)d_in[8];
    const float* bo1   = (const float*)d_in[9];
    const float* Wo2   = (const float*)d_in[10];
    const float* bo2   = (const float*)d_in[11];
    float* out = (float*)d_out;

    (void)in_sizes; (void)n_in; (void)out_size;

    bias_kernel<<<256, 256>>>(rel1, rel2);

    dim3 gq(6, 1024, 2);      // N=768/128, M=131072/128, 2 streams
    qkv_gemm<<<gq, 256>>>(emb1, emb2, Wqkv1, bqkv1, Wqkv2, bqkv2);

    dim3 ga(2048, 8, 2);      // (b*win), head, stream
    attn_kernel<<<ga, 128>>>();

    dim3 gp(2, 1024, 2);      // N=256/128, M=131072/128, 2 streams
    proj_gemm<<<gp, 256>>>(Wo1, bo1, Wo2, bo2, out);
}

// round 4
// speedup vs baseline: 1.0005x; 1.0005x over previous
#include <cuda_runtime.h>
#include <cstdint>

// Problem constants
#define BB 2
#define HH 256
#define WW 256
#define CC 256
#define WS 8
#define SHIFT 4
#define NH 8
#define HD 32
#define OUTC 256
#define NWIN 1024      // (H/WS)*(W/WS)
#define PP 64          // WS*WS
#define MROWS 131072   // B*NWIN*PP per stream

// Scratch (device globals; no runtime allocation allowed)
// qkv layout: [stream][qkv][b][win][head][p][d]
__device__ float g_qkv[2u*3u*BB*NWIN*NH*PP*HD];        // 201,326,592 floats
// attn out layout: [stream][b][win][p][C]  (C = head*32+d)
__device__ float g_attn[2u*BB*NWIN*PP*CC];             // 67,108,864 floats
// bias table: [stream][head][p][q]
__device__ float g_bias[2*NH*PP*PP];                   // 65,536 floats

// ---------------------------------------------------------------------------
// Kernel 0: bias table from rel (NH,15,15)
// ---------------------------------------------------------------------------
__global__ void bias_kernel(const float* __restrict__ rel1,
                            const float* __restrict__ rel2)
{
    int idx = blockIdx.x * blockDim.x + threadIdx.x;   // 0 .. 65535
    int s    = idx >> 15;
    int head = (idx >> 12) & 7;
    int p    = (idx >> 6) & 63;
    int q    = idx & 63;
    const float* rel = s ? rel2 : rel1;
    int a = (p >> 3) - (q >> 3) + 7;
    int b = (p & 7) - (q & 7) + 7;
    g_bias[idx] = rel[head * 225 + a * 15 + b];
}

// ---------------------------------------------------------------------------
// Kernel 1: QKV GEMM with fused roll + window gather.
// A: gathered emb rows (M=131072, K=256)   B: Wqkv (256 x 768)
// 128x128x8 tiling, 256 threads, 8x8 register tiles.
// ---------------------------------------------------------------------------
__global__ __launch_bounds__(256)
void qkv_gemm(const float* __restrict__ emb1, const float* __restrict__ emb2,
              const float* __restrict__ Wqkv1, const float* __restrict__ bqkv1,
              const float* __restrict__ Wqkv2, const float* __restrict__ bqkv2)
{
    const int s = blockIdx.z;
    const float* __restrict__ emb = s ? emb2 : emb1;
    const float* __restrict__ Wq  = s ? Wqkv2 : Wqkv1;
    const float* __restrict__ bq  = s ? bqkv2 : bqkv1;

    __shared__ float As[8][128];   // transposed A tile
    __shared__ float Bs[8][128];

    const int tid      = threadIdx.x;
    const int rowBlock = blockIdx.y;   // 0..1023
    const int colBlock = blockIdx.x;   // 0..5

    // A-tile loader mapping: one float4 per thread per k-iter
    const int arow  = tid >> 1;          // 0..127
    const int apart = (tid & 1) * 4;     // 0 or 4
    const int R     = rowBlock * 128 + arow;
    {
        // decode token -> rolled source pixel
    }
    const int p_   = R & 63;
    const int win_ = (R >> 6) & 1023;
    const int b_   = R >> 16;
    const int hsrc = (((win_ >> 5) << 3) + (p_ >> 3) + SHIFT) & 255;
    const int wsrc = ((win_ & 31) << 3) + (p_ & 7);
    const float* aBase = emb + ((((size_t)b_ * HH + hsrc) * WW + wsrc) * CC);

    // B-tile loader mapping
    const int brow = tid >> 5;          // 0..7
    const int bcol = (tid & 31) * 4;    // 0..124

    float acc[8][8];
#pragma unroll
    for (int i = 0; i < 8; i++)
#pragma unroll
        for (int j = 0; j < 8; j++) acc[i][j] = 0.f;

    const int ty = tid >> 4, tx = tid & 15;

    for (int k0 = 0; k0 < CC; k0 += 8) {
        float4 av = *reinterpret_cast<const float4*>(aBase + k0 + apart);
        float4 bv = *reinterpret_cast<const float4*>(
            Wq + (size_t)(k0 + brow) * 768 + colBlock * 128 + bcol);
        As[apart + 0][arow] = av.x;
        As[apart + 1][arow] = av.y;
        As[apart + 2][arow] = av.z;
        As[apart + 3][arow] = av.w;
        *reinterpret_cast<float4*>(&Bs[brow][bcol]) = bv;
        __syncthreads();
#pragma unroll
        for (int k = 0; k < 8; ++k) {
            float af[8], bf[8];
            *reinterpret_cast<float4*>(&af[0]) = *reinterpret_cast<const float4*>(&As[k][ty * 4]);
            *reinterpret_cast<float4*>(&af[4]) = *reinterpret_cast<const float4*>(&As[k][64 + ty * 4]);
            *reinterpret_cast<float4*>(&bf[0]) = *reinterpret_cast<const float4*>(&Bs[k][tx * 4]);
            *reinterpret_cast<float4*>(&bf[4]) = *reinterpret_cast<const float4*>(&Bs[k][64 + tx * 4]);
#pragma unroll
            for (int i = 0; i < 8; i++)
#pragma unroll
                for (int j = 0; j < 8; j++)
                    acc[i][j] += af[i] * bf[j];
        }
        __syncthreads();
    }

    // epilogue: add bias, scatter to q/k/v layout
#pragma unroll
    for (int ih = 0; ih < 2; ih++) {
#pragma unroll
        for (int i = 0; i < 4; i++) {
            int r  = rowBlock * 128 + ih * 64 + ty * 4 + i;
            int pr = r & 63;
            int wr = (r >> 6) & 1023;
            int br = r >> 16;
#pragma unroll
            for (int jh = 0; jh < 2; jh++) {
#pragma unroll
                for (int j = 0; j < 4; j++) {
                    int n = colBlock * 128 + jh * 64 + tx * 4 + j;   // 0..767
                    float v = acc[ih * 4 + i][jh * 4 + j] + bq[n];
                    int qkv  = n >> 8;
                    int head = (n >> 5) & 7;
                    int d    = n & 31;
                    size_t idx = (((((size_t)s * 3 + qkv) * BB + br) * NWIN + wr) * NH + head)
                                     * ((size_t)PP * HD)
                                 + (size_t)pr * HD + d;
                    g_qkv[idx] = v;
                }
            }
        }
    }
}

// ---------------------------------------------------------------------------
// Kernel 2: windowed cross-attention.
// block = (b*win, head, stream). q from stream s, k/v from stream 1-s.
// ---------------------------------------------------------------------------
__global__ __launch_bounds__(128)
void attn_kernel()
{
    const int s    = blockIdx.z;
    const int head = blockIdx.y;
    const int bw   = blockIdx.x;           // 0..2047
    const int b    = bw >> 10;
    const int win  = bw & 1023;
    const int os   = 1 - s;

    __shared__ float qs[64][36];
    __shared__ float ks[64][36];
    __shared__ float vs[64][36];
    __shared__ float sim[64][65];

    const int tid = threadIdx.x;           // 128 threads

    const size_t tile = (size_t)PP * HD;   // 2048
    const size_t qbase = (((((size_t)s  * 3 + 0) * BB + b) * NWIN + win) * NH + head) * tile;
    const size_t kbase = (((((size_t)os * 3 + 1) * BB + b) * NWIN + win) * NH + head) * tile;
    const size_t vbase = (((((size_t)os * 3 + 2) * BB + b) * NWIN + win) * NH + head) * tile;

    // load q/k/v tiles (2048 floats each)
#pragma unroll
    for (int it = 0; it < 4; ++it) {
        int e = tid * 4 + it * 512;        // float offset, multiple of 4
        int p = e >> 5, d = e & 31;
        float4 vq = *reinterpret_cast<const float4*>(&g_qkv[qbase + e]);
        qs[p][d] = vq.x; qs[p][d+1] = vq.y; qs[p][d+2] = vq.z; qs[p][d+3] = vq.w;
        float4 vk = *reinterpret_cast<const float4*>(&g_qkv[kbase + e]);
        ks[p][d] = vk.x; ks[p][d+1] = vk.y; ks[p][d+2] = vk.z; ks[p][d+3] = vk.w;
        float4 vv = *reinterpret_cast<const float4*>(&g_qkv[vbase + e]);
        vs[p][d] = vv.x; vs[p][d+1] = vv.y; vs[p][d+2] = vv.z; vs[p][d+3] = vv.w;
    }
    // load bias into sim (coalesced)
    const size_t bb = ((size_t)s * NH + head) * 4096;
#pragma unroll
    for (int e = 0; e < 32; ++e) {
        int idx = tid + e * 128;
        sim[idx >> 6][idx & 63] = g_bias[bb + idx];
    }
    __syncthreads();

    // sim = q.k^T * scale + bias, masked
    const int p  = tid >> 1;
    const int qb = (tid & 1) * 32;
    float qreg[32];
#pragma unroll
    for (int d = 0; d < 32; d += 4) {
        float4 v = *reinterpret_cast<const float4*>(&qs[p][d]);
        qreg[d] = v.x; qreg[d+1] = v.y; qreg[d+2] = v.z; qreg[d+3] = v.w;
    }
    const int  ip = p >> 3, jp = p & 7;
    const bool mh = ((win >> 5) == 31);
    const bool mw = ((win & 31) == 31);
    const float scale = 0.17677669529663687f;   // 1/sqrt(32)

#pragma unroll 4
    for (int qi = 0; qi < 32; ++qi) {
        int qq = qb + qi;
        float acc = 0.f;
#pragma unroll
        for (int d = 0; d < 32; d += 4) {
            float4 kv = *reinterpret_cast<const float4*>(&ks[qq][d]);
            acc += qreg[d] * kv.x + qreg[d+1] * kv.y + qreg[d+2] * kv.z + qreg[d+3] * kv.w;
        }
        float bias = sim[p][qq];
        float val  = acc * scale + bias;
        int iq = qq >> 3, jq = qq & 7;
        bool masked = (mh && ((ip < 4) != (iq < 4))) || (mw && ((jp < 4) != (jq < 4)));
        sim[p][qq] = masked ? -1e30f : val;
    }
    __syncthreads();

    // softmax: one thread per row
    if (tid < 64) {
        float m = -1e30f;
#pragma unroll 8
        for (int q = 0; q < 64; ++q) m = fmaxf(m, sim[tid][q]);
        float sum = 0.f;
#pragma unroll 8
        for (int q = 0; q < 64; ++q) {
            float e = __expf(sim[tid][q] - m);
            sim[tid][q] = e;
            sum += e;
        }
        float inv = 1.f / sum;
#pragma unroll 8
        for (int q = 0; q < 64; ++q) sim[tid][q] *= inv;
    }
    __syncthreads();

    // o = pr @ v : thread handles (row p, 16 d-values)
    const int db = (tid & 1) * 16;
    float o[16];
#pragma unroll
    for (int j = 0; j < 16; j++) o[j] = 0.f;
#pragma unroll 4
    for (int qc = 0; qc < 64; ++qc) {
        float pr = sim[p][qc];
#pragma unroll
        for (int j = 0; j < 16; j += 4) {
            float4 vv = *reinterpret_cast<const float4*>(&vs[qc][db + j]);
            o[j]   += pr * vv.x;
            o[j+1] += pr * vv.y;
            o[j+2] += pr * vv.z;
            o[j+3] += pr * vv.w;
        }
    }
    size_t ob = (size_t)s * ((size_t)BB * NWIN * PP * CC)
              + ((((size_t)b * NWIN + win) * PP + p) * CC)
              + (size_t)head * HD + db;
#pragma unroll
    for (int j = 0; j < 16; j += 4) {
        float4 vv = make_float4(o[j], o[j+1], o[j+2], o[j+3]);
        *reinterpret_cast<float4*>(&g_attn[ob + j]) = vv;
    }
}

// ---------------------------------------------------------------------------
// Kernel 3: output projection GEMM + fused unwindow + roll scatter.
// A: g_attn (M=131072, K=256)  B: Wo (256 x 256)
// ---------------------------------------------------------------------------
__global__ __launch_bounds__(256)
void proj_gemm(const float* __restrict__ Wo1, const float* __restrict__ bo1,
               const float* __restrict__ Wo2, const float* __restrict__ bo2,
               float* __restrict__ out)
{
    const int s = blockIdx.z;
    const float* __restrict__ Wo = s ? Wo2 : Wo1;
    const float* __restrict__ bo = s ? bo2 : bo1;
    float* __restrict__ dst = out + (size_t)s * ((size_t)BB * HH * WW * OUTC);

    __shared__ float As[8][128];
    __shared__ float Bs[8][128];

    const int tid      = threadIdx.x;
    const int rowBlock = blockIdx.y;   // 0..1023
    const int colBlock = blockIdx.x;   // 0..1

    const int arow  = tid >> 1;
    const int apart = (tid & 1) * 4;
    const int R     = rowBlock * 128 + arow;
    const float* aBase = g_attn + (size_t)s * ((size_t)BB * NWIN * PP * CC) + (size_t)R * CC;

    const int brow = tid >> 5;
    const int bcol = (tid & 31) * 4;

    float acc[8][8];
#pragma unroll
    for (int i = 0; i < 8; i++)
#pragma unroll
        for (int j = 0; j < 8; j++) acc[i][j] = 0.f;

    const int ty = tid >> 4, tx = tid & 15;

    for (int k0 = 0; k0 < CC; k0 += 8) {
        float4 av = *reinterpret_cast<const float4*>(aBase + k0 + apart);
        float4 bv = *reinterpret_cast<const float4*>(
            Wo + (size_t)(k0 + brow) * OUTC + colBlock * 128 + bcol);
        As[apart + 0][arow] = av.x;
        As[apart + 1][arow] = av.y;
        As[apart + 2][arow] = av.z;
        As[apart + 3][arow] = av.w;
        *reinterpret_cast<float4*>(&Bs[brow][bcol]) = bv;
        __syncthreads();
#pragma unroll
        for (int k = 0; k < 8; ++k) {
            float af[8], bf[8];
            *reinterpret_cast<float4*>(&af[0]) = *reinterpret_cast<const float4*>(&As[k][ty * 4]);
            *reinterpret_cast<float4*>(&af[4]) = *reinterpret_cast<const float4*>(&As[k][64 + ty * 4]);
            *reinterpret_cast<float4*>(&bf[0]) = *reinterpret_cast<const float4*>(&Bs[k][tx * 4]);
            *reinterpret_cast<float4*>(&bf[4]) = *reinterpret_cast<const float4*>(&Bs[k][64 + tx * 4]);
#pragma unroll
            for (int i = 0; i < 8; i++)
#pragma unroll
                for (int j = 0; j < 8; j++)
                    acc[i][j] += af[i] * bf[j];
        }
        __syncthreads();
    }

    // epilogue: add bias, unwindow + roll scatter
#pragma unroll
    for (int ih = 0; ih < 2; ih++) {
#pragma unroll
        for (int i = 0; i < 4; i++) {
            int r  = rowBlock * 128 + ih * 64 + ty * 4 + i;
            int pr = r & 63;
            int wr = (r >> 6) & 1023;
            int br = r >> 16;
            int hout = (((wr >> 5) << 3) + (pr >> 3) + SHIFT) & 255;
            int wout = ((wr & 31) << 3) + (pr & 7);
            size_t rowbase = (((size_t)br * HH + hout) * WW + wout) * OUTC;
#pragma unroll
            for (int jh = 0; jh < 2; jh++) {
                int n0 = colBlock * 128 + jh * 64 + tx * 4;
                float4 vv;
                vv.x = acc[ih * 4 + i][jh * 4 + 0] + bo[n0 + 0];
                vv.y = acc[ih * 4 + i][jh * 4 + 1] + bo[n0 + 1];
                vv.z = acc[ih * 4 + i][jh * 4 + 2] + bo[n0 + 2];
                vv.w = acc[ih * 4 + i][jh * 4 + 3] + bo[n0 + 3];
                *reinterpret_cast<float4*>(&dst[rowbase + n0]) = vv;
            }
        }
    }
}

// ---------------------------------------------------------------------------
// Launch
// ---------------------------------------------------------------------------
extern "C" void kernel_launch(void* const* d_in, const int* in_sizes, int n_in,
                              void* d_out, int out_size)
{
    const float* emb1  = (const float*)d_in[0];
    const float* emb2  = (const float*)d_in[1];
    const float* Wqkv1 = (const float*)d_in[2];
    const float* bqkv1 = (const float*)d_in[3];
    const float* Wqkv2 = (const float*)d_in[4];
    const float* bqkv2 = (const float*)d_in[5];
    const float* rel1  = (const float*)d_in[6];
    const float* rel2  = (const float*)d_in[7];
    const float* Wo1   = (const float*)d_in[8];
    const float* bo1   = (const float*)d_in[9];
    const float* Wo2   = (const float*)d_in[10];
    const float* bo2   = (const float*)d_in[11];
    float* out = (float*)d_out;

    (void)in_sizes; (void)n_in; (void)out_size;

    bias_kernel<<<256, 256>>>(rel1, rel2);

    dim3 gq(6, 1024, 2);      // N=768/128, M=131072/128, 2 streams
    qkv_gemm<<<gq, 256>>>(emb1, emb2, Wqkv1, bqkv1, Wqkv2, bqkv2);

    dim3 ga(2048, 8, 2);      // (b*win), head, stream
    attn_kernel<<<ga, 128>>>();

    dim3 gp(2, 1024, 2);      // N=256/128, M=131072/128, 2 streams
    proj_gemm<<<gp, 256>>>(Wo1, bo1, Wo2, bo2, out);
}